// round 13
// baseline (speedup 1.0000x reference)
#include <cuda_runtime.h>
#include <math.h>

#define SLEN   2048
#define EMB    1024
#define NH     16
#define HD     64
#define NB     2
#define NROWS  (NB*SLEN)      // 4096
#define HALF_WIN 128

// Scratch (device-global arrays: allocation-guard-safe)
__device__ float g_q[(size_t)NB*NH*SLEN*HD];   // (B,H,S,D)
__device__ float g_k[(size_t)NB*NH*SLEN*HD];
__device__ float g_v[(size_t)NB*NH*SLEN*HD];
__device__ float g_att[(size_t)NROWS*EMB];     // (B,S,E)

// ---------------------------------------------------------------------------
// C = A @ W^T + bias.  A: [4096,1024] row-major, W: [1024,1024] row-major (o,e).
// MODE 0: C[r][o] row-major.  MODE 1: scatter to (B,H,S,D).
// 128x128 block tile, K-tile 16, 256 threads, 8x8 micro-tile.
// ---------------------------------------------------------------------------
template<int MODE>
__global__ __launch_bounds__(256)
void gemm_kernel(const float* __restrict__ A, const float* __restrict__ W,
                 const float* __restrict__ bias, float* __restrict__ C)
{
    __shared__ float As[16][132];   // [k][row], pad 132 to soften transpose STS conflicts
    __shared__ float Ws[16][132];   // [k][o]

    const int t  = threadIdx.x;
    const int ty = t >> 4;          // 0..15
    const int tx = t & 15;          // 0..15
    const int r0 = blockIdx.y << 7;
    const int o0 = blockIdx.x << 7;

    float acc[8][8];
    #pragma unroll
    for (int i = 0; i < 8; i++)
        #pragma unroll
        for (int j = 0; j < 8; j++) acc[i][j] = 0.f;

    for (int k0 = 0; k0 < EMB; k0 += 16) {
        // cooperative load + transpose: 128 rows x 16 k, float4 per thread x2 per matrix
        #pragma unroll
        for (int l = 0; l < 2; l++) {
            int fid = t + (l << 8);          // 0..511
            int row = fid >> 2;              // 0..127
            int c4  = (fid & 3) << 2;        // 0,4,8,12
            float4 va = *(const float4*)(A + (long)(r0 + row) * EMB + k0 + c4);
            As[c4 + 0][row] = va.x; As[c4 + 1][row] = va.y;
            As[c4 + 2][row] = va.z; As[c4 + 3][row] = va.w;
            float4 vw = *(const float4*)(W + (long)(o0 + row) * EMB + k0 + c4);
            Ws[c4 + 0][row] = vw.x; Ws[c4 + 1][row] = vw.y;
            Ws[c4 + 2][row] = vw.z; Ws[c4 + 3][row] = vw.w;
        }
        __syncthreads();

        #pragma unroll
        for (int k = 0; k < 16; k++) {
            float4 a0 = *(const float4*)&As[k][ty * 8];
            float4 a1 = *(const float4*)&As[k][ty * 8 + 4];
            float4 b0 = *(const float4*)&Ws[k][tx * 8];
            float4 b1 = *(const float4*)&Ws[k][tx * 8 + 4];
            float a[8] = {a0.x,a0.y,a0.z,a0.w,a1.x,a1.y,a1.z,a1.w};
            float b[8] = {b0.x,b0.y,b0.z,b0.w,b1.x,b1.y,b1.z,b1.w};
            #pragma unroll
            for (int i = 0; i < 8; i++)
                #pragma unroll
                for (int j = 0; j < 8; j++)
                    acc[i][j] += a[i] * b[j];
        }
        __syncthreads();
    }

    #pragma unroll
    for (int i = 0; i < 8; i++) {
        int r = r0 + ty * 8 + i;
        #pragma unroll
        for (int j = 0; j < 8; j++) {
            int o = o0 + tx * 8 + j;
            float v = acc[i][j] + bias[o];
            if (MODE == 0) {
                C[(long)r * EMB + o] = v;
            } else {
                int b = r >> 11;            // r / SLEN
                int s = r & (SLEN - 1);
                int h = o >> 6;             // o / HD
                int d = o & (HD - 1);
                C[(((long)(b * NH + h)) * SLEN + s) * HD + d] = v;
            }
        }
    }
}

// ---------------------------------------------------------------------------
// Attention: per (b,h), Q-tile 128 rows, key tiles of 64, online softmax.
// Mask is ADDITIVE: +1 outside |i-j|<=128, softmax over all keys.
// Threads 256 = 16(ty: query groups of 8) x 16(tx: key groups of 4 / d groups of 4).
// smem: Qs[128][64] row-major, Ks[64][64] d-major (transposed), Vs[64][64] row-major,
//       Ps[128][64] row-major.  All compute LDS/STS patterns bank-conflict-free.
// ---------------------------------------------------------------------------
__global__ __launch_bounds__(256, 2)
void attn_kernel()
{
    extern __shared__ float sm[];
    float* Qs = sm;                   // 128*64
    float* Ks = Qs + 128 * 64;        // 64*64, layout Ks[d*64 + j]
    float* Vs = Ks + 64 * 64;         // 64*64, layout Vs[j*64 + d]
    float* Ps = Vs + 64 * 64;         // 128*64, layout Ps[i*64 + j]

    const int t  = threadIdx.x;
    const int ty = t >> 4;
    const int tx = t & 15;
    const int bh = blockIdx.y;
    const int qbase = blockIdx.x << 7;

    const float* Qg  = g_q + ((long)bh * SLEN + qbase) * HD;
    const float* Kg0 = g_k + (long)bh * SLEN * HD;
    const float* Vg0 = g_v + (long)bh * SLEN * HD;

    // load Q tile (contiguous copy, coalesced, conflict-free)
    #pragma unroll
    for (int l = 0; l < 8; l++) {
        int fid = t + (l << 8);        // 0..2047 float4s
        *(float4*)(Qs + fid * 4) = *(const float4*)(Qg + fid * 4);
    }

    float m[8], lsum[8], o_acc[8][4];
    #pragma unroll
    for (int i = 0; i < 8; i++) {
        m[i] = -1e30f; lsum[i] = 0.f;
        #pragma unroll
        for (int d = 0; d < 4; d++) o_acc[i][d] = 0.f;
    }

    for (int kt = 0; kt < SLEN / 64; kt++) {
        const int kbase = kt * 64;
        __syncthreads();   // protect Ks/Vs/Ps from previous iteration's readers

        // K tile, transposed to d-major.  Lanes take consecutive j -> scalar STS
        // conflict-free; global 16B/256B-stride reads are L1-sector-absorbed.
        const float* Kg = Kg0 + (long)kbase * HD;
        #pragma unroll
        for (int l = 0; l < 4; l++) {
            int fid = t + (l << 8);    // 0..1023
            int j  = fid & 63;
            int d4 = fid >> 6;         // 0..15
            float4 v = *(const float4*)(Kg + j * HD + d4 * 4);
            Ks[(d4 * 4 + 0) * 64 + j] = v.x;
            Ks[(d4 * 4 + 1) * 64 + j] = v.y;
            Ks[(d4 * 4 + 2) * 64 + j] = v.z;
            Ks[(d4 * 4 + 3) * 64 + j] = v.w;
        }
        // V tile, straight copy
        const float* Vg = Vg0 + (long)kbase * HD;
        #pragma unroll
        for (int l = 0; l < 4; l++) {
            int fid = t + (l << 8);
            *(float4*)(Vs + fid * 4) = *(const float4*)(Vg + fid * 4);
        }
        __syncthreads();

        // ---- scores: s[ii][jj] = sum_d Q[i][d] * K[j][d] ----
        float s[8][4];
        #pragma unroll
        for (int i = 0; i < 8; i++)
            #pragma unroll
            for (int j = 0; j < 4; j++) s[i][j] = 0.f;

        #pragma unroll 4
        for (int d4 = 0; d4 < 16; d4++) {
            float4 k0 = *(const float4*)(Ks + (d4 * 4 + 0) * 64 + tx * 4);
            float4 k1 = *(const float4*)(Ks + (d4 * 4 + 1) * 64 + tx * 4);
            float4 k2 = *(const float4*)(Ks + (d4 * 4 + 2) * 64 + tx * 4);
            float4 k3 = *(const float4*)(Ks + (d4 * 4 + 3) * 64 + tx * 4);
            #pragma unroll
            for (int ii = 0; ii < 8; ii++) {
                float4 q = *(const float4*)(Qs + (ty * 8 + ii) * 64 + d4 * 4);
                s[ii][0] += q.x * k0.x + q.y * k1.x + q.z * k2.x + q.w * k3.x;
                s[ii][1] += q.x * k0.y + q.y * k1.y + q.z * k2.y + q.w * k3.y;
                s[ii][2] += q.x * k0.z + q.y * k1.z + q.z * k2.z + q.w * k3.z;
                s[ii][3] += q.x * k0.w + q.y * k1.w + q.z * k2.w + q.w * k3.w;
            }
        }

        // ---- online softmax (rows reduce over 16-lane tx groups) ----
        #pragma unroll
        for (int ii = 0; ii < 8; ii++) {
            int ig = qbase + ty * 8 + ii;
            float v[4];
            #pragma unroll
            for (int jj = 0; jj < 4; jj++) {
                int jg = kbase + tx * 4 + jj;
                int dd = ig - jg; if (dd < 0) dd = -dd;
                v[jj] = s[ii][jj] * 0.125f + ((dd <= HALF_WIN) ? 0.f : 1.f);
            }
            float rmax = fmaxf(fmaxf(v[0], v[1]), fmaxf(v[2], v[3]));
            #pragma unroll
            for (int off = 8; off >= 1; off >>= 1)
                rmax = fmaxf(rmax, __shfl_xor_sync(0xffffffffu, rmax, off));
            float mnew = fmaxf(m[ii], rmax);
            float corr = __expf(m[ii] - mnew);
            float p0 = __expf(v[0] - mnew);
            float p1 = __expf(v[1] - mnew);
            float p2 = __expf(v[2] - mnew);
            float p3 = __expf(v[3] - mnew);
            float rs = p0 + p1 + p2 + p3;
            #pragma unroll
            for (int off = 8; off >= 1; off >>= 1)
                rs += __shfl_xor_sync(0xffffffffu, rs, off);
            lsum[ii] = lsum[ii] * corr + rs;
            m[ii] = mnew;
            o_acc[ii][0] *= corr; o_acc[ii][1] *= corr;
            o_acc[ii][2] *= corr; o_acc[ii][3] *= corr;
            *(float4*)(Ps + (ty * 8 + ii) * 64 + tx * 4) = make_float4(p0, p1, p2, p3);
        }
        __syncthreads();

        // ---- PV: O[i][d] += sum_j P[i][j] * V[j][d] ----
        #pragma unroll 4
        for (int j4 = 0; j4 < 16; j4++) {
            float4 v0 = *(const float4*)(Vs + (j4 * 4 + 0) * 64 + tx * 4);
            float4 v1 = *(const float4*)(Vs + (j4 * 4 + 1) * 64 + tx * 4);
            float4 v2 = *(const float4*)(Vs + (j4 * 4 + 2) * 64 + tx * 4);
            float4 v3 = *(const float4*)(Vs + (j4 * 4 + 3) * 64 + tx * 4);
            #pragma unroll
            for (int ii = 0; ii < 8; ii++) {
                float4 p = *(const float4*)(Ps + (ty * 8 + ii) * 64 + j4 * 4);
                o_acc[ii][0] += p.x * v0.x + p.y * v1.x + p.z * v2.x + p.w * v3.x;
                o_acc[ii][1] += p.x * v0.y + p.y * v1.y + p.z * v2.y + p.w * v3.y;
                o_acc[ii][2] += p.x * v0.z + p.y * v1.z + p.z * v2.z + p.w * v3.z;
                o_acc[ii][3] += p.x * v0.w + p.y * v1.w + p.z * v2.w + p.w * v3.w;
            }
        }
    }

    // write (B,S,E) layout: row = b*S+s, col = h*64 + d
    const int b = bh >> 4;
    const int h = bh & 15;
    #pragma unroll
    for (int ii = 0; ii < 8; ii++) {
        int srow = qbase + ty * 8 + ii;
        float inv = 1.0f / lsum[ii];
        float4 ov = make_float4(o_acc[ii][0] * inv, o_acc[ii][1] * inv,
                                o_acc[ii][2] * inv, o_acc[ii][3] * inv);
        *(float4*)(g_att + ((long)(b * SLEN + srow)) * EMB + h * HD + tx * 4) = ov;
    }
}

// ---------------------------------------------------------------------------
extern "C" void kernel_launch(void* const* d_in, const int* in_sizes, int n_in,
                              void* d_out, int out_size)
{
    (void)in_sizes; (void)n_in; (void)out_size;
    const float* query = (const float*)d_in[0];
    const float* key   = (const float*)d_in[1];
    const float* value = (const float*)d_in[2];
    const float* Wq    = (const float*)d_in[3];
    const float* bq    = (const float*)d_in[4];
    const float* Wk    = (const float*)d_in[5];
    const float* bk    = (const float*)d_in[6];
    const float* Wv    = (const float*)d_in[7];
    const float* bv    = (const float*)d_in[8];
    const float* Wo    = (const float*)d_in[9];
    const float* bo    = (const float*)d_in[10];
    float* out = (float*)d_out;

    float *qp, *kp, *vp, *ap;
    cudaGetSymbolAddress((void**)&qp, g_q);
    cudaGetSymbolAddress((void**)&kp, g_k);
    cudaGetSymbolAddress((void**)&vp, g_v);
    cudaGetSymbolAddress((void**)&ap, g_att);

    // 96 KB dynamic smem for attention (sticky attribute; set before first launch)
    static int smem_bytes = 24576 * (int)sizeof(float);
    cudaFuncSetAttribute(attn_kernel,
                         cudaFuncAttributeMaxDynamicSharedMemorySize, smem_bytes);

    dim3 gg(EMB / 128, NROWS / 128);   // (8, 32)
    gemm_kernel<1><<<gg, 256>>>(query, Wq, bq, qp);
    gemm_kernel<1><<<gg, 256>>>(key,   Wk, bk, kp);
    gemm_kernel<1><<<gg, 256>>>(value, Wv, bv, vp);

    dim3 ga(SLEN / 128, NB * NH);      // (16, 32)
    attn_kernel<<<ga, 256, smem_bytes>>>();

    gemm_kernel<0><<<gg, 256>>>(ap, Wo, bo, out);
}

// round 14
// speedup vs baseline: 1.0006x; 1.0006x over previous
#include <cuda_runtime.h>
#include <math.h>

#define SLEN   2048
#define EMB    1024
#define NH     16
#define HD     64
#define NB     2
#define NROWS  (NB*SLEN)      // 4096
#define HALF_WIN 128

// Scratch (device-global arrays: allocation-guard-safe)
__device__ float g_q[(size_t)NB*NH*SLEN*HD];   // (B,H,S,D)
__device__ float g_k[(size_t)NB*NH*SLEN*HD];
__device__ float g_v[(size_t)NB*NH*SLEN*HD];
__device__ float g_att[(size_t)NROWS*EMB];     // (B,S,E)

// ---------------------------------------------------------------------------
// C = A @ W^T + bias.  A: [4096,1024] row-major, W: [1024,1024] row-major (o,e).
// MODE 0: C[r][o] row-major.  MODE 1: scatter to (B,H,S,D).
// 128x128 block tile, K-tile 16, 256 threads, 8x8 micro-tile.
// ---------------------------------------------------------------------------
template<int MODE>
__global__ __launch_bounds__(256)
void gemm_kernel(const float* __restrict__ A, const float* __restrict__ W,
                 const float* __restrict__ bias, float* __restrict__ C)
{
    __shared__ float As[16][132];   // [k][row], pad 132 to soften transpose STS conflicts
    __shared__ float Ws[16][132];   // [k][o]

    const int t  = threadIdx.x;
    const int ty = t >> 4;          // 0..15
    const int tx = t & 15;          // 0..15
    const int r0 = blockIdx.y << 7;
    const int o0 = blockIdx.x << 7;

    float acc[8][8];
    #pragma unroll
    for (int i = 0; i < 8; i++)
        #pragma unroll
        for (int j = 0; j < 8; j++) acc[i][j] = 0.f;

    for (int k0 = 0; k0 < EMB; k0 += 16) {
        // cooperative load + transpose: 128 rows x 16 k, float4 per thread x2 per matrix
        #pragma unroll
        for (int l = 0; l < 2; l++) {
            int fid = t + (l << 8);          // 0..511
            int row = fid >> 2;              // 0..127
            int c4  = (fid & 3) << 2;        // 0,4,8,12
            float4 va = *(const float4*)(A + (long)(r0 + row) * EMB + k0 + c4);
            As[c4 + 0][row] = va.x; As[c4 + 1][row] = va.y;
            As[c4 + 2][row] = va.z; As[c4 + 3][row] = va.w;
            float4 vw = *(const float4*)(W + (long)(o0 + row) * EMB + k0 + c4);
            Ws[c4 + 0][row] = vw.x; Ws[c4 + 1][row] = vw.y;
            Ws[c4 + 2][row] = vw.z; Ws[c4 + 3][row] = vw.w;
        }
        __syncthreads();

        #pragma unroll
        for (int k = 0; k < 16; k++) {
            float4 a0 = *(const float4*)&As[k][ty * 8];
            float4 a1 = *(const float4*)&As[k][ty * 8 + 4];
            float4 b0 = *(const float4*)&Ws[k][tx * 8];
            float4 b1 = *(const float4*)&Ws[k][tx * 8 + 4];
            float a[8] = {a0.x,a0.y,a0.z,a0.w,a1.x,a1.y,a1.z,a1.w};
            float b[8] = {b0.x,b0.y,b0.z,b0.w,b1.x,b1.y,b1.z,b1.w};
            #pragma unroll
            for (int i = 0; i < 8; i++)
                #pragma unroll
                for (int j = 0; j < 8; j++)
                    acc[i][j] += a[i] * b[j];
        }
        __syncthreads();
    }

    #pragma unroll
    for (int i = 0; i < 8; i++) {
        int r = r0 + ty * 8 + i;
        #pragma unroll
        for (int j = 0; j < 8; j++) {
            int o = o0 + tx * 8 + j;
            float v = acc[i][j] + bias[o];
            if (MODE == 0) {
                C[(long)r * EMB + o] = v;
            } else {
                int b = r >> 11;            // r / SLEN
                int s = r & (SLEN - 1);
                int h = o >> 6;             // o / HD
                int d = o & (HD - 1);
                C[(((long)(b * NH + h)) * SLEN + s) * HD + d] = v;
            }
        }
    }
}

// ---------------------------------------------------------------------------
// Attention: per (b,h), Q-tile 128 rows, key tiles of 64, online softmax.
// Mask is ADDITIVE: +1 outside |i-j|<=128, softmax over all keys.
// Threads 256 = 16(ty: query groups of 8) x 16(tx: key groups of 4 / d groups of 4).
// smem: Qs[128][64] row-major, Ks[64][64] d-major (transposed), Vs[64][64] row-major,
//       Ps[128][64] row-major.  All compute LDS/STS patterns bank-conflict-free.
// ---------------------------------------------------------------------------
__global__ __launch_bounds__(256, 2)
void attn_kernel()
{
    extern __shared__ float sm[];
    float* Qs = sm;                   // 128*64
    float* Ks = Qs + 128 * 64;        // 64*64, layout Ks[d*64 + j]
    float* Vs = Ks + 64 * 64;         // 64*64, layout Vs[j*64 + d]
    float* Ps = Vs + 64 * 64;         // 128*64, layout Ps[i*64 + j]

    const int t  = threadIdx.x;
    const int ty = t >> 4;
    const int tx = t & 15;
    const int bh = blockIdx.y;
    const int qbase = blockIdx.x << 7;

    const float* Qg  = g_q + ((long)bh * SLEN + qbase) * HD;
    const float* Kg0 = g_k + (long)bh * SLEN * HD;
    const float* Vg0 = g_v + (long)bh * SLEN * HD;

    // load Q tile (contiguous copy, coalesced, conflict-free)
    #pragma unroll
    for (int l = 0; l < 8; l++) {
        int fid = t + (l << 8);        // 0..2047 float4s
        *(float4*)(Qs + fid * 4) = *(const float4*)(Qg + fid * 4);
    }

    float m[8], lsum[8], o_acc[8][4];
    #pragma unroll
    for (int i = 0; i < 8; i++) {
        m[i] = -1e30f; lsum[i] = 0.f;
        #pragma unroll
        for (int d = 0; d < 4; d++) o_acc[i][d] = 0.f;
    }

    for (int kt = 0; kt < SLEN / 64; kt++) {
        const int kbase = kt * 64;
        __syncthreads();   // protect Ks/Vs/Ps from previous iteration's readers

        // K tile, transposed to d-major.  Lanes take consecutive j -> scalar STS
        // conflict-free; global 16B/256B-stride reads are L1-sector-absorbed.
        const float* Kg = Kg0 + (long)kbase * HD;
        #pragma unroll
        for (int l = 0; l < 4; l++) {
            int fid = t + (l << 8);    // 0..1023
            int j  = fid & 63;
            int d4 = fid >> 6;         // 0..15
            float4 v = *(const float4*)(Kg + j * HD + d4 * 4);
            Ks[(d4 * 4 + 0) * 64 + j] = v.x;
            Ks[(d4 * 4 + 1) * 64 + j] = v.y;
            Ks[(d4 * 4 + 2) * 64 + j] = v.z;
            Ks[(d4 * 4 + 3) * 64 + j] = v.w;
        }
        // V tile, straight copy
        const float* Vg = Vg0 + (long)kbase * HD;
        #pragma unroll
        for (int l = 0; l < 4; l++) {
            int fid = t + (l << 8);
            *(float4*)(Vs + fid * 4) = *(const float4*)(Vg + fid * 4);
        }
        __syncthreads();

        // ---- scores: s[ii][jj] = sum_d Q[i][d] * K[j][d] ----
        float s[8][4];
        #pragma unroll
        for (int i = 0; i < 8; i++)
            #pragma unroll
            for (int j = 0; j < 4; j++) s[i][j] = 0.f;

        #pragma unroll 4
        for (int d4 = 0; d4 < 16; d4++) {
            float4 k0 = *(const float4*)(Ks + (d4 * 4 + 0) * 64 + tx * 4);
            float4 k1 = *(const float4*)(Ks + (d4 * 4 + 1) * 64 + tx * 4);
            float4 k2 = *(const float4*)(Ks + (d4 * 4 + 2) * 64 + tx * 4);
            float4 k3 = *(const float4*)(Ks + (d4 * 4 + 3) * 64 + tx * 4);
            #pragma unroll
            for (int ii = 0; ii < 8; ii++) {
                float4 q = *(const float4*)(Qs + (ty * 8 + ii) * 64 + d4 * 4);
                s[ii][0] += q.x * k0.x + q.y * k1.x + q.z * k2.x + q.w * k3.x;
                s[ii][1] += q.x * k0.y + q.y * k1.y + q.z * k2.y + q.w * k3.y;
                s[ii][2] += q.x * k0.z + q.y * k1.z + q.z * k2.z + q.w * k3.z;
                s[ii][3] += q.x * k0.w + q.y * k1.w + q.z * k2.w + q.w * k3.w;
            }
        }

        // ---- online softmax (rows reduce over 16-lane tx groups) ----
        #pragma unroll
        for (int ii = 0; ii < 8; ii++) {
            int ig = qbase + ty * 8 + ii;
            float v[4];
            #pragma unroll
            for (int jj = 0; jj < 4; jj++) {
                int jg = kbase + tx * 4 + jj;
                int dd = ig - jg; if (dd < 0) dd = -dd;
                v[jj] = s[ii][jj] * 0.125f + ((dd <= HALF_WIN) ? 0.f : 1.f);
            }
            float rmax = fmaxf(fmaxf(v[0], v[1]), fmaxf(v[2], v[3]));
            #pragma unroll
            for (int off = 8; off >= 1; off >>= 1)
                rmax = fmaxf(rmax, __shfl_xor_sync(0xffffffffu, rmax, off));
            float mnew = fmaxf(m[ii], rmax);
            float corr = __expf(m[ii] - mnew);
            float p0 = __expf(v[0] - mnew);
            float p1 = __expf(v[1] - mnew);
            float p2 = __expf(v[2] - mnew);
            float p3 = __expf(v[3] - mnew);
            float rs = p0 + p1 + p2 + p3;
            #pragma unroll
            for (int off = 8; off >= 1; off >>= 1)
                rs += __shfl_xor_sync(0xffffffffu, rs, off);
            lsum[ii] = lsum[ii] * corr + rs;
            m[ii] = mnew;
            o_acc[ii][0] *= corr; o_acc[ii][1] *= corr;
            o_acc[ii][2] *= corr; o_acc[ii][3] *= corr;
            *(float4*)(Ps + (ty * 8 + ii) * 64 + tx * 4) = make_float4(p0, p1, p2, p3);
        }
        __syncthreads();

        // ---- PV: O[i][d] += sum_j P[i][j] * V[j][d] ----
        #pragma unroll 4
        for (int j4 = 0; j4 < 16; j4++) {
            float4 v0 = *(const float4*)(Vs + (j4 * 4 + 0) * 64 + tx * 4);
            float4 v1 = *(const float4*)(Vs + (j4 * 4 + 1) * 64 + tx * 4);
            float4 v2 = *(const float4*)(Vs + (j4 * 4 + 2) * 64 + tx * 4);
            float4 v3 = *(const float4*)(Vs + (j4 * 4 + 3) * 64 + tx * 4);
            #pragma unroll
            for (int ii = 0; ii < 8; ii++) {
                float4 p = *(const float4*)(Ps + (ty * 8 + ii) * 64 + j4 * 4);
                o_acc[ii][0] += p.x * v0.x + p.y * v1.x + p.z * v2.x + p.w * v3.x;
                o_acc[ii][1] += p.x * v0.y + p.y * v1.y + p.z * v2.y + p.w * v3.y;
                o_acc[ii][2] += p.x * v0.z + p.y * v1.z + p.z * v2.z + p.w * v3.z;
                o_acc[ii][3] += p.x * v0.w + p.y * v1.w + p.z * v2.w + p.w * v3.w;
            }
        }
    }

    // write (B,S,E) layout: row = b*S+s, col = h*64 + d
    const int b = bh >> 4;
    const int h = bh & 15;
    #pragma unroll
    for (int ii = 0; ii < 8; ii++) {
        int srow = qbase + ty * 8 + ii;
        float inv = 1.0f / lsum[ii];
        float4 ov = make_float4(o_acc[ii][0] * inv, o_acc[ii][1] * inv,
                                o_acc[ii][2] * inv, o_acc[ii][3] * inv);
        *(float4*)(g_att + ((long)(b * SLEN + srow)) * EMB + h * HD + tx * 4) = ov;
    }
}

// ---------------------------------------------------------------------------
extern "C" void kernel_launch(void* const* d_in, const int* in_sizes, int n_in,
                              void* d_out, int out_size)
{
    (void)in_sizes; (void)n_in; (void)out_size;
    const float* query = (const float*)d_in[0];
    const float* key   = (const float*)d_in[1];
    const float* value = (const float*)d_in[2];
    const float* Wq    = (const float*)d_in[3];
    const float* bq    = (const float*)d_in[4];
    const float* Wk    = (const float*)d_in[5];
    const float* bk    = (const float*)d_in[6];
    const float* Wv    = (const float*)d_in[7];
    const float* bv    = (const float*)d_in[8];
    const float* Wo    = (const float*)d_in[9];
    const float* bo    = (const float*)d_in[10];
    float* out = (float*)d_out;

    float *qp, *kp, *vp, *ap;
    cudaGetSymbolAddress((void**)&qp, g_q);
    cudaGetSymbolAddress((void**)&kp, g_k);
    cudaGetSymbolAddress((void**)&vp, g_v);
    cudaGetSymbolAddress((void**)&ap, g_att);

    // 96 KB dynamic smem for attention (sticky attribute; set before first launch)
    static int smem_bytes = 24576 * (int)sizeof(float);
    cudaFuncSetAttribute(attn_kernel,
                         cudaFuncAttributeMaxDynamicSharedMemorySize, smem_bytes);

    dim3 gg(EMB / 128, NROWS / 128);   // (8, 32)
    gemm_kernel<1><<<gg, 256>>>(query, Wq, bq, qp);
    gemm_kernel<1><<<gg, 256>>>(key,   Wk, bk, kp);
    gemm_kernel<1><<<gg, 256>>>(value, Wv, bv, vp);

    dim3 ga(SLEN / 128, NB * NH);      // (16, 32)
    attn_kernel<<<ga, 256, smem_bytes>>>();

    gemm_kernel<0><<<gg, 256>>>(ap, Wo, bo, out);
}

// round 15
// speedup vs baseline: 1.0295x; 1.0289x over previous
#include <cuda_runtime.h>
#include <math.h>

#define SLEN   2048
#define EMB    1024
#define NH     16
#define HD     64
#define NB     2
#define NROWS  (NB*SLEN)      // 4096
#define HALF_WIN 128

// Scratch (device-global arrays: allocation-guard-safe)
__device__ float g_q[(size_t)NB*NH*SLEN*HD];   // (B,H,S,D)
__device__ float g_k[(size_t)NB*NH*SLEN*HD];
__device__ float g_v[(size_t)NB*NH*SLEN*HD];
__device__ float g_att[(size_t)NROWS*EMB];     // (B,S,E)

// ---------------------------------------------------------------------------
// Packed f32x2 helpers (sm_103a FFMA2 path — ptxas never emits from C++)
// Lane order: low 32 bits = element 0 (matches memory order of a b64 load).
// ---------------------------------------------------------------------------
__device__ __forceinline__ unsigned long long pack2(float lo, float hi) {
    unsigned long long r;
    asm("mov.b64 %0, {%1, %2};" : "=l"(r) : "f"(lo), "f"(hi));
    return r;
}
__device__ __forceinline__ unsigned long long bcast2(float v) {
    unsigned long long r;
    asm("mov.b64 %0, {%1, %1};" : "=l"(r) : "f"(v));
    return r;
}
__device__ __forceinline__ void unpack2(unsigned long long v, float& lo, float& hi) {
    asm("mov.b64 {%0, %1}, %2;" : "=f"(lo), "=f"(hi) : "l"(v));
}
__device__ __forceinline__ void ffma2(unsigned long long& d,
                                      unsigned long long a, unsigned long long b) {
    asm("fma.rn.f32x2 %0, %1, %2, %0;" : "+l"(d) : "l"(a), "l"(b));
}
__device__ __forceinline__ void fmul2(unsigned long long& d, unsigned long long a) {
    asm("mul.rn.f32x2 %0, %0, %1;" : "+l"(d) : "l"(a));
}

// ---------------------------------------------------------------------------
// C = A @ W^T + bias.  A: [4096,1024] row-major, W: [1024,1024] row-major (o,e).
// MODE 0: C[r][o] row-major.  MODE 1: scatter to (B,H,S,D).
// 128x128 block tile, K-tile 16, 256 threads, 8x8 micro-tile (FFMA2: 8x4 pairs).
// ---------------------------------------------------------------------------
template<int MODE>
__global__ __launch_bounds__(256)
void gemm_kernel(const float* __restrict__ A, const float* __restrict__ W,
                 const float* __restrict__ bias, float* __restrict__ C)
{
    __shared__ float As[16][132];   // [k][row], pad 132 (132*4=528, 16B-mult)
    __shared__ float Ws[16][132];   // [k][o]

    const int t  = threadIdx.x;
    const int ty = t >> 4;          // 0..15
    const int tx = t & 15;          // 0..15
    const int r0 = blockIdx.y << 7;
    const int o0 = blockIdx.x << 7;

    unsigned long long acc2[8][4];  // pairs along o
    #pragma unroll
    for (int i = 0; i < 8; i++)
        #pragma unroll
        for (int j = 0; j < 4; j++) acc2[i][j] = 0ull;

    for (int k0 = 0; k0 < EMB; k0 += 16) {
        #pragma unroll
        for (int l = 0; l < 2; l++) {
            int fid = t + (l << 8);          // 0..511
            int row = fid >> 2;              // 0..127
            int c4  = (fid & 3) << 2;        // 0,4,8,12
            float4 va = *(const float4*)(A + (long)(r0 + row) * EMB + k0 + c4);
            As[c4 + 0][row] = va.x; As[c4 + 1][row] = va.y;
            As[c4 + 2][row] = va.z; As[c4 + 3][row] = va.w;
            float4 vw = *(const float4*)(W + (long)(o0 + row) * EMB + k0 + c4);
            Ws[c4 + 0][row] = vw.x; Ws[c4 + 1][row] = vw.y;
            Ws[c4 + 2][row] = vw.z; Ws[c4 + 3][row] = vw.w;
        }
        __syncthreads();

        #pragma unroll
        for (int k = 0; k < 16; k++) {
            float4 a0 = *(const float4*)&As[k][ty * 8];
            float4 a1 = *(const float4*)&As[k][ty * 8 + 4];
            // B pairs load natively as 64-bit (same addresses as float4 path)
            ulonglong2 bA = *(const ulonglong2*)&Ws[k][tx * 8];
            ulonglong2 bB = *(const ulonglong2*)&Ws[k][tx * 8 + 4];
            unsigned long long bv[4] = {bA.x, bA.y, bB.x, bB.y};
            unsigned long long av[8];
            av[0]=bcast2(a0.x); av[1]=bcast2(a0.y); av[2]=bcast2(a0.z); av[3]=bcast2(a0.w);
            av[4]=bcast2(a1.x); av[5]=bcast2(a1.y); av[6]=bcast2(a1.z); av[7]=bcast2(a1.w);
            #pragma unroll
            for (int i = 0; i < 8; i++)
                #pragma unroll
                for (int j = 0; j < 4; j++)
                    ffma2(acc2[i][j], av[i], bv[j]);
        }
        __syncthreads();
    }

    #pragma unroll
    for (int i = 0; i < 8; i++) {
        int r = r0 + ty * 8 + i;
        #pragma unroll
        for (int j4 = 0; j4 < 4; j4++) {
            float vlo, vhi;
            unpack2(acc2[i][j4], vlo, vhi);
            int o = o0 + tx * 8 + j4 * 2;
            float c0 = vlo + bias[o];
            float c1 = vhi + bias[o + 1];
            if (MODE == 0) {
                C[(long)r * EMB + o]     = c0;
                C[(long)r * EMB + o + 1] = c1;
            } else {
                int b = r >> 11;
                int s = r & (SLEN - 1);
                int h = o >> 6;
                int d = o & (HD - 1);
                long base = (((long)(b * NH + h)) * SLEN + s) * HD + d;
                C[base]     = c0;
                C[base + 1] = c1;   // same h (o even, HD=64)
            }
        }
    }
}

// ---------------------------------------------------------------------------
// Attention: per (b,h), Q-tile 128 rows, key tiles of 64, online softmax.
// Mask is ADDITIVE: +1 outside |i-j|<=128, softmax over all keys.
// Threads 256 = 16(ty: query groups of 8) x 16(tx: key groups of 4 / d groups of 4).
// smem: Qs[128][64] row-major, Ks[64][64] d-major, Vs[64][64] row-major,
//       Ps[128][64] row-major.  Same verified conflict-free patterns; the
//       float4 loads are reinterpreted as ulonglong2 for native f32x2 pairs.
// ---------------------------------------------------------------------------
__global__ __launch_bounds__(256, 2)
void attn_kernel()
{
    extern __shared__ float sm[];
    float* Qs = sm;                   // 128*64
    float* Ks = Qs + 128 * 64;        // 64*64, layout Ks[d*64 + j]
    float* Vs = Ks + 64 * 64;         // 64*64, layout Vs[j*64 + d]
    float* Ps = Vs + 64 * 64;         // 128*64, layout Ps[i*64 + j]

    const int t  = threadIdx.x;
    const int ty = t >> 4;
    const int tx = t & 15;
    const int bh = blockIdx.y;
    const int qbase = blockIdx.x << 7;

    const float* Qg  = g_q + ((long)bh * SLEN + qbase) * HD;
    const float* Kg0 = g_k + (long)bh * SLEN * HD;
    const float* Vg0 = g_v + (long)bh * SLEN * HD;

    #pragma unroll
    for (int l = 0; l < 8; l++) {
        int fid = t + (l << 8);
        *(float4*)(Qs + fid * 4) = *(const float4*)(Qg + fid * 4);
    }

    float m[8], lsum[8];
    unsigned long long o2[8][2];      // packed pairs along d
    #pragma unroll
    for (int i = 0; i < 8; i++) {
        m[i] = -1e30f; lsum[i] = 0.f;
        o2[i][0] = 0ull; o2[i][1] = 0ull;
    }

    for (int kt = 0; kt < SLEN / 64; kt++) {
        const int kbase = kt * 64;
        __syncthreads();

        const float* Kg = Kg0 + (long)kbase * HD;
        #pragma unroll
        for (int l = 0; l < 4; l++) {
            int fid = t + (l << 8);
            int j  = fid & 63;
            int d4 = fid >> 6;
            float4 v = *(const float4*)(Kg + j * HD + d4 * 4);
            Ks[(d4 * 4 + 0) * 64 + j] = v.x;
            Ks[(d4 * 4 + 1) * 64 + j] = v.y;
            Ks[(d4 * 4 + 2) * 64 + j] = v.z;
            Ks[(d4 * 4 + 3) * 64 + j] = v.w;
        }
        const float* Vg = Vg0 + (long)kbase * HD;
        #pragma unroll
        for (int l = 0; l < 4; l++) {
            int fid = t + (l << 8);
            *(float4*)(Vs + fid * 4) = *(const float4*)(Vg + fid * 4);
        }
        __syncthreads();

        // ---- scores with FFMA2: pairs along j ----
        unsigned long long s2[8][2];
        #pragma unroll
        for (int i = 0; i < 8; i++) { s2[i][0] = 0ull; s2[i][1] = 0ull; }

        #pragma unroll 4
        for (int d4 = 0; d4 < 16; d4++) {
            // each .x = (j0,j1) pair, .y = (j2,j3) pair for one d-component
            ulonglong2 k0 = *(const ulonglong2*)(Ks + (d4 * 4 + 0) * 64 + tx * 4);
            ulonglong2 k1 = *(const ulonglong2*)(Ks + (d4 * 4 + 1) * 64 + tx * 4);
            ulonglong2 k2 = *(const ulonglong2*)(Ks + (d4 * 4 + 2) * 64 + tx * 4);
            ulonglong2 k3 = *(const ulonglong2*)(Ks + (d4 * 4 + 3) * 64 + tx * 4);
            #pragma unroll
            for (int ii = 0; ii < 8; ii++) {
                float4 q = *(const float4*)(Qs + (ty * 8 + ii) * 64 + d4 * 4);
                unsigned long long qx = bcast2(q.x), qy = bcast2(q.y);
                unsigned long long qz = bcast2(q.z), qw = bcast2(q.w);
                ffma2(s2[ii][0], qx, k0.x); ffma2(s2[ii][1], qx, k0.y);
                ffma2(s2[ii][0], qy, k1.x); ffma2(s2[ii][1], qy, k1.y);
                ffma2(s2[ii][0], qz, k2.x); ffma2(s2[ii][1], qz, k2.y);
                ffma2(s2[ii][0], qw, k3.x); ffma2(s2[ii][1], qw, k3.y);
            }
        }

        // ---- online softmax (rows reduce over 16-lane tx groups) ----
        #pragma unroll
        for (int ii = 0; ii < 8; ii++) {
            int ig = qbase + ty * 8 + ii;
            float v[4];
            unpack2(s2[ii][0], v[0], v[1]);
            unpack2(s2[ii][1], v[2], v[3]);
            #pragma unroll
            for (int jj = 0; jj < 4; jj++) {
                int jg = kbase + tx * 4 + jj;
                int dd = ig - jg; if (dd < 0) dd = -dd;
                v[jj] = v[jj] * 0.125f + ((dd <= HALF_WIN) ? 0.f : 1.f);
            }
            float rmax = fmaxf(fmaxf(v[0], v[1]), fmaxf(v[2], v[3]));
            #pragma unroll
            for (int off = 8; off >= 1; off >>= 1)
                rmax = fmaxf(rmax, __shfl_xor_sync(0xffffffffu, rmax, off));
            float mnew = fmaxf(m[ii], rmax);
            float corr = __expf(m[ii] - mnew);
            float p0 = __expf(v[0] - mnew);
            float p1 = __expf(v[1] - mnew);
            float p2 = __expf(v[2] - mnew);
            float p3 = __expf(v[3] - mnew);
            float rs = p0 + p1 + p2 + p3;
            #pragma unroll
            for (int off = 8; off >= 1; off >>= 1)
                rs += __shfl_xor_sync(0xffffffffu, rs, off);
            lsum[ii] = lsum[ii] * corr + rs;
            m[ii] = mnew;
            unsigned long long c2 = bcast2(corr);
            fmul2(o2[ii][0], c2);
            fmul2(o2[ii][1], c2);
            *(float4*)(Ps + (ty * 8 + ii) * 64 + tx * 4) = make_float4(p0, p1, p2, p3);
        }
        __syncthreads();

        // ---- PV with FFMA2: pairs along d ----
        #pragma unroll 4
        for (int j4 = 0; j4 < 16; j4++) {
            // each .x = (d0,d1) pair, .y = (d2,d3) pair for one j row
            ulonglong2 v0 = *(const ulonglong2*)(Vs + (j4 * 4 + 0) * 64 + tx * 4);
            ulonglong2 v1 = *(const ulonglong2*)(Vs + (j4 * 4 + 1) * 64 + tx * 4);
            ulonglong2 v2 = *(const ulonglong2*)(Vs + (j4 * 4 + 2) * 64 + tx * 4);
            ulonglong2 v3 = *(const ulonglong2*)(Vs + (j4 * 4 + 3) * 64 + tx * 4);
            #pragma unroll
            for (int ii = 0; ii < 8; ii++) {
                float4 p = *(const float4*)(Ps + (ty * 8 + ii) * 64 + j4 * 4);
                unsigned long long px = bcast2(p.x), py = bcast2(p.y);
                unsigned long long pz = bcast2(p.z), pw = bcast2(p.w);
                ffma2(o2[ii][0], px, v0.x); ffma2(o2[ii][1], px, v0.y);
                ffma2(o2[ii][0], py, v1.x); ffma2(o2[ii][1], py, v1.y);
                ffma2(o2[ii][0], pz, v2.x); ffma2(o2[ii][1], pz, v2.y);
                ffma2(o2[ii][0], pw, v3.x); ffma2(o2[ii][1], pw, v3.y);
            }
        }
    }

    // write (B,S,E) layout: row = b*S+s, col = h*64 + d
    const int b = bh >> 4;
    const int h = bh & 15;
    #pragma unroll
    for (int ii = 0; ii < 8; ii++) {
        int srow = qbase + ty * 8 + ii;
        float inv = 1.0f / lsum[ii];
        float o0l, o0h, o1l, o1h;
        unpack2(o2[ii][0], o0l, o0h);
        unpack2(o2[ii][1], o1l, o1h);
        float4 ov = make_float4(o0l * inv, o0h * inv, o1l * inv, o1h * inv);
        *(float4*)(g_att + ((long)(b * SLEN + srow)) * EMB + h * HD + tx * 4) = ov;
    }
}

// ---------------------------------------------------------------------------
extern "C" void kernel_launch(void* const* d_in, const int* in_sizes, int n_in,
                              void* d_out, int out_size)
{
    (void)in_sizes; (void)n_in; (void)out_size;
    const float* query = (const float*)d_in[0];
    const float* key   = (const float*)d_in[1];
    const float* value = (const float*)d_in[2];
    const float* Wq    = (const float*)d_in[3];
    const float* bq    = (const float*)d_in[4];
    const float* Wk    = (const float*)d_in[5];
    const float* bk    = (const float*)d_in[6];
    const float* Wv    = (const float*)d_in[7];
    const float* bv    = (const float*)d_in[8];
    const float* Wo    = (const float*)d_in[9];
    const float* bo    = (const float*)d_in[10];
    float* out = (float*)d_out;

    float *qp, *kp, *vp, *ap;
    cudaGetSymbolAddress((void**)&qp, g_q);
    cudaGetSymbolAddress((void**)&kp, g_k);
    cudaGetSymbolAddress((void**)&vp, g_v);
    cudaGetSymbolAddress((void**)&ap, g_att);

    static int smem_bytes = 24576 * (int)sizeof(float);
    cudaFuncSetAttribute(attn_kernel,
                         cudaFuncAttributeMaxDynamicSharedMemorySize, smem_bytes);

    dim3 gg(EMB / 128, NROWS / 128);   // (8, 32)
    gemm_kernel<1><<<gg, 256>>>(query, Wq, bq, qp);
    gemm_kernel<1><<<gg, 256>>>(key,   Wk, bk, kp);
    gemm_kernel<1><<<gg, 256>>>(value, Wv, bv, vp);

    dim3 ga(SLEN / 128, NB * NH);      // (16, 32)
    attn_kernel<<<ga, 256, smem_bytes>>>();

    gemm_kernel<0><<<gg, 256>>>(ap, Wo, bo, out);
}